// round 12
// baseline (speedup 1.0000x reference)
#include <cuda_runtime.h>
#include <math.h>

#define N 8192
#define D 32
#define NUM_ITERS 100
#define EPSF 0.1f
#define STABF 1e-8f
#define INV_N (1.0f / 8192.0f)

// ---------------------------------------------------------------------------
// Static device scratch (allocation-free per harness rules).
// 4 x 256MB fp32 Gibbs kernel matrices + vectors + reduction partials.
// ---------------------------------------------------------------------------
__device__ float g_Kst[(size_t)N * N];  // rows = source, cols = target
__device__ float g_Kts[(size_t)N * N];  // exact transpose of g_Kst (recomputed, bit-identical)
__device__ float g_Kss[(size_t)N * N];  // symmetric
__device__ float g_Ktt[(size_t)N * N];  // symmetric
__device__ float g_u[3 * N];
__device__ float g_v[3 * N];
__device__ double g_part[3 * N];

// ---------------------------------------------------------------------------
// Init u = 1 (reference scan starts from ones; v is overwritten first).
// ---------------------------------------------------------------------------
__global__ void init_u_kernel() {
    for (int i = blockIdx.x * blockDim.x + threadIdx.x; i < 3 * N;
         i += gridDim.x * blockDim.x)
        g_u[i] = 1.0f;
}

// ---------------------------------------------------------------------------
// Build the 4 Gibbs kernel matrices: K[i][j] = exp(-max(|ai|^2+|bj|^2-2 ai.bj, 0)/eps)
// Block: 128 A-rows cached in SMEM; each thread owns one column j per chunk
// with b_j in registers. FMA-bound (~0.5ms total), B streamed through L2.
// grid = (N/128, 4), 256 threads.
// ---------------------------------------------------------------------------
__global__ __launch_bounds__(256) void build_kernels(const float* __restrict__ src,
                                                     const float* __restrict__ tgt) {
    const int m = blockIdx.y;
    const float* A;
    const float* B;
    float* K;
    if (m == 0)      { A = src; B = tgt; K = g_Kst; }
    else if (m == 1) { A = tgt; B = src; K = g_Kts; }
    else if (m == 2) { A = src; B = src; K = g_Kss; }
    else             { A = tgt; B = tgt; K = g_Ktt; }

    __shared__ float sA[128 * D];
    __shared__ float sNA[128];
    const int rowBase = blockIdx.x * 128;

    for (int idx = threadIdx.x; idx < 128 * D; idx += 256)
        sA[idx] = A[(size_t)rowBase * D + idx];
    __syncthreads();
    for (int i = threadIdx.x; i < 128; i += 256) {
        float s = 0.f;
#pragma unroll
        for (int k = 0; k < D; k++) s = fmaf(sA[i * D + k], sA[i * D + k], s);
        sNA[i] = s;
    }
    __syncthreads();

    for (int jBase = 0; jBase < N; jBase += 256) {
        const int j = jBase + threadIdx.x;
        float bb[D];
        const float4* bp = (const float4*)(B + (size_t)j * D);
#pragma unroll
        for (int q = 0; q < D / 4; q++) {
            float4 t = bp[q];
            bb[q * 4 + 0] = t.x; bb[q * 4 + 1] = t.y;
            bb[q * 4 + 2] = t.z; bb[q * 4 + 3] = t.w;
        }
        float nb = 0.f;
#pragma unroll
        for (int k = 0; k < D; k++) nb = fmaf(bb[k], bb[k], nb);

#pragma unroll 4
        for (int i = 0; i < 128; i++) {
            float dot = 0.f;
#pragma unroll
            for (int k = 0; k < D; k++) dot = fmaf(sA[i * D + k], bb[k], dot);
            float d = sNA[i] + nb - 2.0f * dot;
            d = fmaxf(d, 0.0f);
            K[(size_t)(rowBase + i) * N + j] = expf(d * (-1.0f / EPSF));
        }
    }
}

// ---------------------------------------------------------------------------
// One Sinkhorn half-step for all 3 problems:
//   phase 0: v = nu / (K^T u + stab)  -> stream {Kts, Kss, Ktt} rows
//   phase 1: u = mu / (K  v + stab)   -> stream {Kst, Kss, Ktt} rows
// Warp-per-row (2 rows/warp, 16 rows/block), vector staged in 32KB SMEM and
// reused across 16 rows => DRAM-bound stream, no per-row block barriers.
// grid = (N/16, 3), 256 threads. ~816MB per launch.
// ---------------------------------------------------------------------------
__global__ __launch_bounds__(256) void half_step(int phase) {
    const int p = blockIdx.y;
    const float* M;
    const float* x;
    float* y;
    if (phase == 0) {
        M = (p == 0) ? g_Kts : (p == 1) ? g_Kss : g_Ktt;
        x = g_u + p * N;
        y = g_v + p * N;
    } else {
        M = (p == 0) ? g_Kst : (p == 1) ? g_Kss : g_Ktt;
        x = g_v + p * N;
        y = g_u + p * N;
    }

    __shared__ float4 xs4[N / 4];  // 32KB
    const float4* x4 = (const float4*)x;
    for (int i = threadIdx.x; i < N / 4; i += 256) xs4[i] = x4[i];
    __syncthreads();

    const int warp = threadIdx.x >> 5;
    const int lane = threadIdx.x & 31;

#pragma unroll
    for (int r = 0; r < 2; r++) {
        const int row = blockIdx.x * 16 + warp * 2 + r;
        const float4* Mr = (const float4*)(M + (size_t)row * N);
        float acc = 0.f;
#pragma unroll 8
        for (int i = 0; i < (N / 4) / 32; i++) {  // 64 float4 per lane
            const int idx = lane + i * 32;
            float4 mv = Mr[idx];
            float4 xv = xs4[idx];
            acc = fmaf(mv.x, xv.x, acc);
            acc = fmaf(mv.y, xv.y, acc);
            acc = fmaf(mv.z, xv.z, acc);
            acc = fmaf(mv.w, xv.w, acc);
        }
#pragma unroll
        for (int o = 16; o > 0; o >>= 1)
            acc += __shfl_xor_sync(0xffffffffu, acc, o);
        if (lane == 0) y[row] = INV_N / (acc + STABF);
    }
}

// ---------------------------------------------------------------------------
// Final transport cost, stage 1: per-row  part[row] = u_row * sum_j K*v_j*cost
// cost recovered as -eps * log(K) (K in [exp(-20), 1], always positive).
// Double promoted at the warp reduction; fixed-order => deterministic.
// grid = (N/16, 3), 256 threads.
// ---------------------------------------------------------------------------
__global__ __launch_bounds__(256) void cost_rows() {
    const int p = blockIdx.y;
    const float* M = (p == 0) ? g_Kst : (p == 1) ? g_Kss : g_Ktt;
    const float* v = g_v + p * N;
    const float* u = g_u + p * N;

    __shared__ float4 vs4[N / 4];
    const float4* v4 = (const float4*)v;
    for (int i = threadIdx.x; i < N / 4; i += 256) vs4[i] = v4[i];
    __syncthreads();

    const int warp = threadIdx.x >> 5;
    const int lane = threadIdx.x & 31;

#pragma unroll
    for (int r = 0; r < 2; r++) {
        const int row = blockIdx.x * 16 + warp * 2 + r;
        const float4* Mr = (const float4*)(M + (size_t)row * N);
        float acc = 0.f;
#pragma unroll 4
        for (int i = 0; i < (N / 4) / 32; i++) {
            const int idx = lane + i * 32;
            float4 kv = Mr[idx];
            float4 vv = vs4[idx];
            acc = fmaf(kv.x * vv.x, -EPSF * __logf(kv.x), acc);
            acc = fmaf(kv.y * vv.y, -EPSF * __logf(kv.y), acc);
            acc = fmaf(kv.z * vv.z, -EPSF * __logf(kv.z), acc);
            acc = fmaf(kv.w * vv.w, -EPSF * __logf(kv.w), acc);
        }
        double dacc = (double)acc;
#pragma unroll
        for (int o = 16; o > 0; o >>= 1)
            dacc += __shfl_xor_sync(0xffffffffu, dacc, o);
        if (lane == 0) g_part[p * N + row] = dacc * (double)u[row];
    }
}

// ---------------------------------------------------------------------------
// Final stage 2: deterministic single-block reduction of the 3x8192 partials,
// then debiased divergence / n.
// ---------------------------------------------------------------------------
__global__ __launch_bounds__(256) void final_reduce(float* __restrict__ out) {
    __shared__ double sred[3][8];
    const int warp = threadIdx.x >> 5;
    const int lane = threadIdx.x & 31;

    for (int p = 0; p < 3; p++) {
        double s = 0.0;
        for (int i = threadIdx.x; i < N; i += 256) s += g_part[p * N + i];
#pragma unroll
        for (int o = 16; o > 0; o >>= 1)
            s += __shfl_xor_sync(0xffffffffu, s, o);
        if (lane == 0) sred[p][warp] = s;
    }
    __syncthreads();
    if (threadIdx.x == 0) {
        double w[3];
        for (int p = 0; p < 3; p++) {
            double s = 0.0;
            for (int q = 0; q < 8; q++) s += sred[p][q];
            w[p] = s;
        }
        double cost = w[0] - 0.5 * w[1] - 0.5 * w[2];
        out[0] = (float)(cost / (double)N);
    }
}

// ---------------------------------------------------------------------------
// kernel_launch: pure kernel launches, graph-capturable, allocation-free.
// ---------------------------------------------------------------------------
extern "C" void kernel_launch(void* const* d_in, const int* in_sizes, int n_in,
                              void* d_out, int out_size) {
    const float* src = (const float*)d_in[0];
    const float* tgt = (const float*)d_in[1];
    float* out = (float*)d_out;

    init_u_kernel<<<24, 256>>>();
    build_kernels<<<dim3(N / 128, 4), 256>>>(src, tgt);

    for (int t = 0; t < NUM_ITERS; t++) {
        half_step<<<dim3(N / 16, 3), 256>>>(0);
        half_step<<<dim3(N / 16, 3), 256>>>(1);
    }

    cost_rows<<<dim3(N / 16, 3), 256>>>();
    final_reduce<<<1, 256>>>(out);
}

// round 13
// speedup vs baseline: 1.7699x; 1.7699x over previous
#include <cuda_runtime.h>
#include <cuda_fp16.h>
#include <math.h>

#define N 8192
#define D 32
#define NUM_ITERS 100
#define EPSF 0.1f
#define STABF 1e-8f
#define INV_N (1.0f / 8192.0f)

// ---------------------------------------------------------------------------
// Static device scratch (allocation-free per harness rules).
// 4 x 128MB fp16 Gibbs kernel matrices + fp32 vectors + reduction partials.
// fp16 storage halves the 150GB Sinkhorn streaming floor; rounding noise is
// i.i.d. and washes out under the doubly-stochastic plan (see analysis).
// ---------------------------------------------------------------------------
__device__ __half g_Kst[(size_t)N * N];  // rows = source, cols = target
__device__ __half g_Kts[(size_t)N * N];  // transpose of g_Kst (recomputed, bit-identical)
__device__ __half g_Kss[(size_t)N * N];  // symmetric
__device__ __half g_Ktt[(size_t)N * N];  // symmetric
__device__ float g_u[3 * N];
__device__ float g_v[3 * N];
__device__ double g_part[3 * N];

// ---------------------------------------------------------------------------
// Init u = 1 (reference scan starts from ones; v is overwritten first).
// ---------------------------------------------------------------------------
__global__ void init_u_kernel() {
    for (int i = blockIdx.x * blockDim.x + threadIdx.x; i < 3 * N;
         i += gridDim.x * blockDim.x)
        g_u[i] = 1.0f;
}

// ---------------------------------------------------------------------------
// Build the 4 Gibbs kernel matrices: K[i][j] = fp16(exp(-max(|ai|^2+|bj|^2-2ai.bj,0)/eps))
// 128 A-rows cached in SMEM; each thread owns one column j with b_j in regs.
// FMA order over k identical for Kst and Kts => bit-identical transpose.
// grid = (N/128, 4), 256 threads.
// ---------------------------------------------------------------------------
__global__ __launch_bounds__(256) void build_kernels(const float* __restrict__ src,
                                                     const float* __restrict__ tgt) {
    const int m = blockIdx.y;
    const float* A;
    const float* B;
    __half* K;
    if (m == 0)      { A = src; B = tgt; K = g_Kst; }
    else if (m == 1) { A = tgt; B = src; K = g_Kts; }
    else if (m == 2) { A = src; B = src; K = g_Kss; }
    else             { A = tgt; B = tgt; K = g_Ktt; }

    __shared__ float sA[128 * D];
    __shared__ float sNA[128];
    const int rowBase = blockIdx.x * 128;

    for (int idx = threadIdx.x; idx < 128 * D; idx += 256)
        sA[idx] = A[(size_t)rowBase * D + idx];
    __syncthreads();
    for (int i = threadIdx.x; i < 128; i += 256) {
        float s = 0.f;
#pragma unroll
        for (int k = 0; k < D; k++) s = fmaf(sA[i * D + k], sA[i * D + k], s);
        sNA[i] = s;
    }
    __syncthreads();

    for (int jBase = 0; jBase < N; jBase += 256) {
        const int j = jBase + threadIdx.x;
        float bb[D];
        const float4* bp = (const float4*)(B + (size_t)j * D);
#pragma unroll
        for (int q = 0; q < D / 4; q++) {
            float4 t = bp[q];
            bb[q * 4 + 0] = t.x; bb[q * 4 + 1] = t.y;
            bb[q * 4 + 2] = t.z; bb[q * 4 + 3] = t.w;
        }
        float nb = 0.f;
#pragma unroll
        for (int k = 0; k < D; k++) nb = fmaf(bb[k], bb[k], nb);

#pragma unroll 4
        for (int i = 0; i < 128; i++) {
            float dot = 0.f;
#pragma unroll
            for (int k = 0; k < D; k++) dot = fmaf(sA[i * D + k], bb[k], dot);
            float d = sNA[i] + nb - 2.0f * dot;
            d = fmaxf(d, 0.0f);
            K[(size_t)(rowBase + i) * N + j] = __float2half_rn(expf(d * (-1.0f / EPSF)));
        }
    }
}

// ---------------------------------------------------------------------------
// fp16 uint4 (8 halves) dot with 8 fp32 x values, fp32 accumulate.
// ---------------------------------------------------------------------------
__device__ __forceinline__ float dot8h(uint4 a, float4 x0, float4 x1, float acc) {
    float2 f;
    f = __half22float2(*reinterpret_cast<const __half2*>(&a.x));
    acc = fmaf(f.x, x0.x, acc); acc = fmaf(f.y, x0.y, acc);
    f = __half22float2(*reinterpret_cast<const __half2*>(&a.y));
    acc = fmaf(f.x, x0.z, acc); acc = fmaf(f.y, x0.w, acc);
    f = __half22float2(*reinterpret_cast<const __half2*>(&a.z));
    acc = fmaf(f.x, x1.x, acc); acc = fmaf(f.y, x1.y, acc);
    f = __half22float2(*reinterpret_cast<const __half2*>(&a.w));
    acc = fmaf(f.x, x1.z, acc); acc = fmaf(f.y, x1.w, acc);
    return acc;
}

// ---------------------------------------------------------------------------
// One Sinkhorn half-step for all 3 problems:
//   phase 0: v = nu / (K^T u + stab)  -> stream {Kts, Kss, Ktt} rows
//   phase 1: u = mu / (K  v + stab)   -> stream {Kst, Kss, Ktt} rows
// Warp-per-2-rows, interleaved (2 independent LDG streams), x staged in 32KB
// SMEM and reused across 16 rows/block. 384MB fp16 stream per launch.
// grid = (N/16, 3), 256 threads.
// ---------------------------------------------------------------------------
__global__ __launch_bounds__(256) void half_step(int phase) {
    const int p = blockIdx.y;
    const __half* M;
    const float* x;
    float* y;
    if (phase == 0) {
        M = (p == 0) ? g_Kts : (p == 1) ? g_Kss : g_Ktt;
        x = g_u + p * N;
        y = g_v + p * N;
    } else {
        M = (p == 0) ? g_Kst : (p == 1) ? g_Kss : g_Ktt;
        x = g_v + p * N;
        y = g_u + p * N;
    }

    __shared__ float4 xs4[N / 4];  // 32KB fp32 multiplier vector
    const float4* x4 = (const float4*)x;
    for (int i = threadIdx.x; i < N / 4; i += 256) xs4[i] = x4[i];
    __syncthreads();

    const int warp = threadIdx.x >> 5;
    const int lane = threadIdx.x & 31;
    const int row0 = blockIdx.x * 16 + warp * 2;

    const uint4* M0 = (const uint4*)(M + (size_t)row0 * N);
    const uint4* M1 = (const uint4*)(M + (size_t)(row0 + 1) * N);

    float acc0 = 0.f, acc1 = 0.f;
#pragma unroll 4
    for (int i = 0; i < (N / 8) / 32; i++) {  // 32 iters, 2 x 16B loads each
        const int idx = lane + i * 32;
        uint4 a = M0[idx];
        uint4 b = M1[idx];
        float4 x0 = xs4[2 * idx];
        float4 x1 = xs4[2 * idx + 1];
        acc0 = dot8h(a, x0, x1, acc0);
        acc1 = dot8h(b, x0, x1, acc1);
    }
#pragma unroll
    for (int o = 16; o > 0; o >>= 1) {
        acc0 += __shfl_xor_sync(0xffffffffu, acc0, o);
        acc1 += __shfl_xor_sync(0xffffffffu, acc1, o);
    }
    if (lane == 0) {
        y[row0]     = INV_N / (acc0 + STABF);
        y[row0 + 1] = INV_N / (acc1 + STABF);
    }
}

// ---------------------------------------------------------------------------
// Final transport cost, stage 1: per-row  part[row] = u_row * sum_j K*v_j*cost
// cost recovered as -eps * log(K); log arg clamped so a flushed K=0 term
// contributes exactly 0 (0 * finite) instead of NaN.
// grid = (N/16, 3), 256 threads.
// ---------------------------------------------------------------------------
__global__ __launch_bounds__(256) void cost_rows() {
    const int p = blockIdx.y;
    const __half* M = (p == 0) ? g_Kst : (p == 1) ? g_Kss : g_Ktt;
    const float* v = g_v + p * N;
    const float* u = g_u + p * N;

    __shared__ float4 vs4[N / 4];
    const float4* v4 = (const float4*)v;
    for (int i = threadIdx.x; i < N / 4; i += 256) vs4[i] = v4[i];
    __syncthreads();

    const int warp = threadIdx.x >> 5;
    const int lane = threadIdx.x & 31;

#pragma unroll
    for (int r = 0; r < 2; r++) {
        const int row = blockIdx.x * 16 + warp * 2 + r;
        const uint4* Mr = (const uint4*)(M + (size_t)row * N);
        float acc = 0.f;
        for (int i = 0; i < (N / 8) / 32; i++) {
            const int idx = lane + i * 32;
            uint4 a = Mr[idx];
            float4 x0 = vs4[2 * idx];
            float4 x1 = vs4[2 * idx + 1];
            float kf[8];
            float2 f;
            f = __half22float2(*reinterpret_cast<const __half2*>(&a.x));
            kf[0] = f.x; kf[1] = f.y;
            f = __half22float2(*reinterpret_cast<const __half2*>(&a.y));
            kf[2] = f.x; kf[3] = f.y;
            f = __half22float2(*reinterpret_cast<const __half2*>(&a.z));
            kf[4] = f.x; kf[5] = f.y;
            f = __half22float2(*reinterpret_cast<const __half2*>(&a.w));
            kf[6] = f.x; kf[7] = f.y;
            const float xv[8] = {x0.x, x0.y, x0.z, x0.w, x1.x, x1.y, x1.z, x1.w};
#pragma unroll
            for (int q = 0; q < 8; q++) {
                float c = -EPSF * __logf(fmaxf(kf[q], 1e-30f));
                acc = fmaf(kf[q] * xv[q], c, acc);
            }
        }
        double dacc = (double)acc;
#pragma unroll
        for (int o = 16; o > 0; o >>= 1)
            dacc += __shfl_xor_sync(0xffffffffu, dacc, o);
        if (lane == 0) g_part[p * N + row] = dacc * (double)u[row];
    }
}

// ---------------------------------------------------------------------------
// Final stage 2: deterministic single-block reduction of the 3x8192 partials,
// then debiased divergence / n.
// ---------------------------------------------------------------------------
__global__ __launch_bounds__(256) void final_reduce(float* __restrict__ out) {
    __shared__ double sred[3][8];
    const int warp = threadIdx.x >> 5;
    const int lane = threadIdx.x & 31;

    for (int p = 0; p < 3; p++) {
        double s = 0.0;
        for (int i = threadIdx.x; i < N; i += 256) s += g_part[p * N + i];
#pragma unroll
        for (int o = 16; o > 0; o >>= 1)
            s += __shfl_xor_sync(0xffffffffu, s, o);
        if (lane == 0) sred[p][warp] = s;
    }
    __syncthreads();
    if (threadIdx.x == 0) {
        double w[3];
        for (int p = 0; p < 3; p++) {
            double s = 0.0;
            for (int q = 0; q < 8; q++) s += sred[p][q];
            w[p] = s;
        }
        double cost = w[0] - 0.5 * w[1] - 0.5 * w[2];
        out[0] = (float)(cost / (double)N);
    }
}

// ---------------------------------------------------------------------------
// kernel_launch: pure kernel launches, graph-capturable, allocation-free.
// ---------------------------------------------------------------------------
extern "C" void kernel_launch(void* const* d_in, const int* in_sizes, int n_in,
                              void* d_out, int out_size) {
    const float* src = (const float*)d_in[0];
    const float* tgt = (const float*)d_in[1];
    float* out = (float*)d_out;

    init_u_kernel<<<24, 256>>>();
    build_kernels<<<dim3(N / 128, 4), 256>>>(src, tgt);

    for (int t = 0; t < NUM_ITERS; t++) {
        half_step<<<dim3(N / 16, 3), 256>>>(0);
        half_step<<<dim3(N / 16, 3), 256>>>(1);
    }

    cost_rows<<<dim3(N / 16, 3), 256>>>();
    final_reduce<<<1, 256>>>(out);
}

// round 14
// speedup vs baseline: 3.3922x; 1.9167x over previous
#include <cuda_runtime.h>
#include <cuda_fp16.h>
#include <math.h>

#define N 8192
#define D 32
#define NUM_ITERS 100
#define EPSF 0.1f
#define STABF 1e-8f
#define INV_N (1.0f / 8192.0f)

// fp8 e4m3 storage scale: K' = 64*K maps K in [~4e-3, 1] to [0.25, 64],
// inside e4m3 normal range [1.56e-2, 448]. Folded exactly into updates.
#define KSCALE 64.0f
#define INV_KSCALE (1.0f / 64.0f)

// ---------------------------------------------------------------------------
// Static device scratch (allocation-free). 4 x 64MB fp8 Gibbs matrices,
// declared as uint4 arrays to guarantee 16B alignment for vector loads.
// ---------------------------------------------------------------------------
__device__ uint4 g_Kst4[(size_t)N * N / 16];  // rows = source, cols = target
__device__ uint4 g_Kts4[(size_t)N * N / 16];  // transpose (recomputed, bit-identical)
__device__ uint4 g_Kss4[(size_t)N * N / 16];  // symmetric
__device__ uint4 g_Ktt4[(size_t)N * N / 16];  // symmetric
__device__ float g_u[3 * N];
__device__ float g_v[3 * N];
__device__ double g_part[3 * N];

// ---------------------------------------------------------------------------
// fp32 -> e4m3 (satfinite), single byte.
// ---------------------------------------------------------------------------
__device__ __forceinline__ unsigned char f32_to_e4m3(float f) {
    unsigned short r;
    asm("cvt.rn.satfinite.e4m3x2.f32 %0, %1, %2;" : "=h"(r) : "f"(f), "f"(f));
    return (unsigned char)r;
}

// 4 fp8 (one 32-bit word) dot 4 fp32, fp32 accumulate. e4m3->f16 is exact.
__device__ __forceinline__ float dotword(unsigned w, float4 x, float acc) {
    unsigned h0, h1;
    asm("{\n\t"
        ".reg .b16 lo, hi;\n\t"
        "mov.b32 {lo, hi}, %2;\n\t"
        "cvt.rn.f16x2.e4m3x2 %0, lo;\n\t"
        "cvt.rn.f16x2.e4m3x2 %1, hi;\n\t"
        "}"
        : "=r"(h0), "=r"(h1) : "r"(w));
    float2 f01 = __half22float2(*reinterpret_cast<__half2*>(&h0));
    float2 f23 = __half22float2(*reinterpret_cast<__half2*>(&h1));
    acc = fmaf(f01.x, x.x, acc);
    acc = fmaf(f01.y, x.y, acc);
    acc = fmaf(f23.x, x.z, acc);
    acc = fmaf(f23.y, x.w, acc);
    return acc;
}

// Unpack one fp8 word to 4 floats (true K = K'/64).
__device__ __forceinline__ float4 word_to_k(unsigned w) {
    unsigned h0, h1;
    asm("{\n\t"
        ".reg .b16 lo, hi;\n\t"
        "mov.b32 {lo, hi}, %2;\n\t"
        "cvt.rn.f16x2.e4m3x2 %0, lo;\n\t"
        "cvt.rn.f16x2.e4m3x2 %1, hi;\n\t"
        "}"
        : "=r"(h0), "=r"(h1) : "r"(w));
    float2 f01 = __half22float2(*reinterpret_cast<__half2*>(&h0));
    float2 f23 = __half22float2(*reinterpret_cast<__half2*>(&h1));
    return make_float4(f01.x * INV_KSCALE, f01.y * INV_KSCALE,
                       f23.x * INV_KSCALE, f23.y * INV_KSCALE);
}

// ---------------------------------------------------------------------------
// Init u = 1 (reference scan starts from ones; v is overwritten first).
// ---------------------------------------------------------------------------
__global__ void init_u_kernel() {
    for (int i = blockIdx.x * blockDim.x + threadIdx.x; i < 3 * N;
         i += gridDim.x * blockDim.x)
        g_u[i] = 1.0f;
}

// ---------------------------------------------------------------------------
// Build the 4 Gibbs matrices: K'[i][j] = e4m3(64 * exp(-max(...,0)/eps)).
// FMA order over k identical for Kst and Kts => bit-identical transpose.
// grid = (N/128, 4), 256 threads.
// ---------------------------------------------------------------------------
__global__ __launch_bounds__(256) void build_kernels(const float* __restrict__ src,
                                                     const float* __restrict__ tgt) {
    const int m = blockIdx.y;
    const float* A;
    const float* B;
    unsigned char* K;
    if (m == 0)      { A = src; B = tgt; K = (unsigned char*)g_Kst4; }
    else if (m == 1) { A = tgt; B = src; K = (unsigned char*)g_Kts4; }
    else if (m == 2) { A = src; B = src; K = (unsigned char*)g_Kss4; }
    else             { A = tgt; B = tgt; K = (unsigned char*)g_Ktt4; }

    __shared__ float sA[128 * D];
    __shared__ float sNA[128];
    const int rowBase = blockIdx.x * 128;

    for (int idx = threadIdx.x; idx < 128 * D; idx += 256)
        sA[idx] = A[(size_t)rowBase * D + idx];
    __syncthreads();
    for (int i = threadIdx.x; i < 128; i += 256) {
        float s = 0.f;
#pragma unroll
        for (int k = 0; k < D; k++) s = fmaf(sA[i * D + k], sA[i * D + k], s);
        sNA[i] = s;
    }
    __syncthreads();

    for (int jBase = 0; jBase < N; jBase += 256) {
        const int j = jBase + threadIdx.x;
        float bb[D];
        const float4* bp = (const float4*)(B + (size_t)j * D);
#pragma unroll
        for (int q = 0; q < D / 4; q++) {
            float4 t = bp[q];
            bb[q * 4 + 0] = t.x; bb[q * 4 + 1] = t.y;
            bb[q * 4 + 2] = t.z; bb[q * 4 + 3] = t.w;
        }
        float nb = 0.f;
#pragma unroll
        for (int k = 0; k < D; k++) nb = fmaf(bb[k], bb[k], nb);

#pragma unroll 4
        for (int i = 0; i < 128; i++) {
            float dot = 0.f;
#pragma unroll
            for (int k = 0; k < D; k++) dot = fmaf(sA[i * D + k], bb[k], dot);
            float d = sNA[i] + nb - 2.0f * dot;
            d = fmaxf(d, 0.0f);
            K[(size_t)(rowBase + i) * N + j] =
                f32_to_e4m3(expf(d * (-1.0f / EPSF)) * KSCALE);
        }
    }
}

// ---------------------------------------------------------------------------
// One Sinkhorn half-step for all 3 problems (fp8 K', fp32 x/accumulate):
//   phase 0: v = nu / (K^T u + stab)  -> stream {Kts, Kss, Ktt} rows
//   phase 1: u = mu / (K  v + stab)   -> stream {Kst, Kss, Ktt} rows
// Scale fold: acc = 64*(Kx) => y = (64/N)/(acc + 64*stab).
// x staged in 4 deinterleaved smem arrays: every LDS.128 is 16B-strided
// across lanes => zero bank conflicts (fixes R12's 8-way conflict).
// 512 threads, 2 rows/warp => 32 rows/block. grid = (N/32, 3). 192MB/launch.
// ---------------------------------------------------------------------------
__global__ __launch_bounds__(512) void half_step(int phase) {
    const int p = blockIdx.y;
    const uint4* M;
    const float* x;
    float* y;
    if (phase == 0) {
        M = (p == 0) ? g_Kts4 : (p == 1) ? g_Kss4 : g_Ktt4;
        x = g_u + p * N;
        y = g_v + p * N;
    } else {
        M = (p == 0) ? g_Kst4 : (p == 1) ? g_Kss4 : g_Ktt4;
        x = g_v + p * N;
        y = g_u + p * N;
    }

    // Deinterleaved x: slot s covers columns 16s..16s+15.
    __shared__ float4 xsA[N / 16], xsB[N / 16], xsC[N / 16], xsD[N / 16];
    {
        const float4* x4 = (const float4*)x;
        for (int j = threadIdx.x; j < N / 4; j += 512) {
            float4 f = x4[j];
            const int s = j >> 2, q = j & 3;
            if (q == 0)      xsA[s] = f;
            else if (q == 1) xsB[s] = f;
            else if (q == 2) xsC[s] = f;
            else             xsD[s] = f;
        }
    }
    __syncthreads();

    const int warp = threadIdx.x >> 5;
    const int lane = threadIdx.x & 31;
    const int row0 = blockIdx.x * 32 + warp * 2;

    const uint4* M0 = M + (size_t)row0 * (N / 16);
    const uint4* M1 = M + (size_t)(row0 + 1) * (N / 16);

    float acc0 = 0.f, acc1 = 0.f;
#pragma unroll 4
    for (int i = 0; i < 16; i++) {  // 16 iters x 16 fp8/lane/row
        const int idx = lane + i * 32;
        uint4 a = M0[idx];
        uint4 b = M1[idx];
        float4 xA = xsA[idx], xB = xsB[idx], xC = xsC[idx], xD = xsD[idx];
        acc0 = dotword(a.x, xA, acc0);
        acc1 = dotword(b.x, xA, acc1);
        acc0 = dotword(a.y, xB, acc0);
        acc1 = dotword(b.y, xB, acc1);
        acc0 = dotword(a.z, xC, acc0);
        acc1 = dotword(b.z, xC, acc1);
        acc0 = dotword(a.w, xD, acc0);
        acc1 = dotword(b.w, xD, acc1);
    }
#pragma unroll
    for (int o = 16; o > 0; o >>= 1) {
        acc0 += __shfl_xor_sync(0xffffffffu, acc0, o);
        acc1 += __shfl_xor_sync(0xffffffffu, acc1, o);
    }
    if (lane == 0) {
        // y = INV_N / (acc/64 + stab) = (INV_N*64)/(acc + 64*stab)
        y[row0]     = (INV_N * KSCALE) / (acc0 + STABF * KSCALE);
        y[row0 + 1] = (INV_N * KSCALE) / (acc1 + STABF * KSCALE);
    }
}

// ---------------------------------------------------------------------------
// Final transport cost: part[row] = u_row * sum_j K*v_j*(-eps*log K).
// K recovered from fp8 K'/64; log arg clamped so flushed K'=0 contributes
// exactly 0 (factor K=0 multiplies a finite c). One-shot kernel.
// grid = (N/16, 3), 256 threads.
// ---------------------------------------------------------------------------
__global__ __launch_bounds__(256) void cost_rows() {
    const int p = blockIdx.y;
    const uint4* M = (p == 0) ? g_Kst4 : (p == 1) ? g_Kss4 : g_Ktt4;
    const float* v = g_v + p * N;
    const float* u = g_u + p * N;

    __shared__ float4 vsA[N / 16], vsB[N / 16], vsC[N / 16], vsD[N / 16];
    {
        const float4* v4 = (const float4*)v;
        for (int j = threadIdx.x; j < N / 4; j += 256) {
            float4 f = v4[j];
            const int s = j >> 2, q = j & 3;
            if (q == 0)      vsA[s] = f;
            else if (q == 1) vsB[s] = f;
            else if (q == 2) vsC[s] = f;
            else             vsD[s] = f;
        }
    }
    __syncthreads();

    const int warp = threadIdx.x >> 5;
    const int lane = threadIdx.x & 31;

#pragma unroll
    for (int r = 0; r < 2; r++) {
        const int row = blockIdx.x * 16 + warp * 2 + r;
        const uint4* Mr = M + (size_t)row * (N / 16);
        float acc = 0.f;
        for (int i = 0; i < 16; i++) {
            const int idx = lane + i * 32;
            uint4 a = Mr[idx];
            float4 k0 = word_to_k(a.x);
            float4 k1 = word_to_k(a.y);
            float4 k2 = word_to_k(a.z);
            float4 k3 = word_to_k(a.w);
            float4 x0 = vsA[idx], x1 = vsB[idx], x2 = vsC[idx], x3 = vsD[idx];
            const float kf[16] = {k0.x, k0.y, k0.z, k0.w, k1.x, k1.y, k1.z, k1.w,
                                  k2.x, k2.y, k2.z, k2.w, k3.x, k3.y, k3.z, k3.w};
            const float xv[16] = {x0.x, x0.y, x0.z, x0.w, x1.x, x1.y, x1.z, x1.w,
                                  x2.x, x2.y, x2.z, x2.w, x3.x, x3.y, x3.z, x3.w};
#pragma unroll
            for (int q = 0; q < 16; q++) {
                float c = -EPSF * __logf(fmaxf(kf[q], 1e-30f));
                acc = fmaf(kf[q] * xv[q], c, acc);
            }
        }
        double dacc = (double)acc;
#pragma unroll
        for (int o = 16; o > 0; o >>= 1)
            dacc += __shfl_xor_sync(0xffffffffu, dacc, o);
        if (lane == 0) g_part[p * N + row] = dacc * (double)u[row];
    }
}

// ---------------------------------------------------------------------------
// Final stage 2: deterministic single-block reduction of 3x8192 partials,
// then debiased divergence / n.
// ---------------------------------------------------------------------------
__global__ __launch_bounds__(256) void final_reduce(float* __restrict__ out) {
    __shared__ double sred[3][8];
    const int warp = threadIdx.x >> 5;
    const int lane = threadIdx.x & 31;

    for (int p = 0; p < 3; p++) {
        double s = 0.0;
        for (int i = threadIdx.x; i < N; i += 256) s += g_part[p * N + i];
#pragma unroll
        for (int o = 16; o > 0; o >>= 1)
            s += __shfl_xor_sync(0xffffffffu, s, o);
        if (lane == 0) sred[p][warp] = s;
    }
    __syncthreads();
    if (threadIdx.x == 0) {
        double w[3];
        for (int p = 0; p < 3; p++) {
            double s = 0.0;
            for (int q = 0; q < 8; q++) s += sred[p][q];
            w[p] = s;
        }
        double cost = w[0] - 0.5 * w[1] - 0.5 * w[2];
        out[0] = (float)(cost / (double)N);
    }
}

// ---------------------------------------------------------------------------
// kernel_launch: pure kernel launches, graph-capturable, allocation-free.
// ---------------------------------------------------------------------------
extern "C" void kernel_launch(void* const* d_in, const int* in_sizes, int n_in,
                              void* d_out, int out_size) {
    const float* src = (const float*)d_in[0];
    const float* tgt = (const float*)d_in[1];
    float* out = (float*)d_out;

    init_u_kernel<<<24, 256>>>();
    build_kernels<<<dim3(N / 128, 4), 256>>>(src, tgt);

    for (int t = 0; t < NUM_ITERS; t++) {
        half_step<<<dim3(N / 32, 3), 512>>>(0);
        half_step<<<dim3(N / 32, 3), 512>>>(1);
    }

    cost_rows<<<dim3(N / 16, 3), 256>>>();
    final_reduce<<<1, 256>>>(out);
}